// round 8
// baseline (speedup 1.0000x reference)
#include <cuda_runtime.h>
#include <cstdint>
#include <math.h>

#define B_ 16
#define R_ 1024
#define F_ 128
#define D_ 128
#define K_ 7
#define H_ 512
#define H2_ 256
#define FEAT_ 263   // 2*D + K
#define NB1_ 32     // k1 blocks per batch (32 rows each)
#define NB3_ 32     // k3 blocks per batch (32 rows each)
#define TILE_FLOATS 7168   // 8 rows x 896

// ---------------- device scratch (static, allocation-free) ----------------
__device__ float E_g[B_ * R_ * F_];          // exp(masked S)
__device__ float Zrow_g[B_ * R_];            // sum_f E*mexf
__device__ float pscore_g[B_ * R_];          // S.sum(f) * pm
__device__ float Zcolp_g[B_ * NB1_ * F_];    // partial: sum_r E*mexr
__device__ float ligcolp_g[B_ * NB1_ * F_];  // partial: sum_r S
__device__ float abarp_g[B_ * NB1_ * F_];    // partial: sum_r coef_r*E
__device__ float tstrp_g[B_ * NB1_ * 8];     // partial type strength
__device__ float Pwp_g[B_ * NB3_ * D_];      // partial: sum_r pscore_r*P  (unscaled)
__device__ float Cwp_g[B_ * NB3_ * D_];      // partial: sum_r craw_r*P    (unscaled)

// ---------------- helpers ----------------
__device__ __forceinline__ float warpSum(float v) {
    #pragma unroll
    for (int o = 16; o > 0; o >>= 1) v += __shfl_down_sync(0xffffffffu, v, o);
    return v;
}
__device__ __forceinline__ float warpAllSum(float v) {
    #pragma unroll
    for (int o = 16; o > 0; o >>= 1) v += __shfl_xor_sync(0xffffffffu, v, o);
    return v;
}
__device__ __forceinline__ float blockReduceSum(float v, float* sm) {
    int lane = threadIdx.x & 31, w = threadIdx.x >> 5;
    int nw = (blockDim.x + 31) >> 5;
    v = warpSum(v);
    if (lane == 0) sm[w] = v;
    __syncthreads();
    float r = (threadIdx.x < nw) ? sm[threadIdx.x] : 0.0f;
    if (w == 0) r = warpSum(r);
    if (threadIdx.x == 0) sm[0] = r;
    __syncthreads();
    r = sm[0];
    __syncthreads();
    return r;
}
__device__ __forceinline__ void l2pf(const void* p) {
    asm volatile("prefetch.global.L2 [%0];" :: "l"(p));
}
__device__ __forceinline__ void cpasync16(unsigned int saddr, const void* gptr) {
    asm volatile("cp.async.cg.shared.global [%0], [%1], 16;" :: "r"(saddr), "l"(gptr));
}
__device__ __forceinline__ void cpasync_commit() {
    asm volatile("cp.async.commit_group;" ::: "memory");
}
template<int N>
__device__ __forceinline__ void cpasync_wait() {
    asm volatile("cp.async.wait_group %0;" :: "n"(N) : "memory");
}

// ============ K1: logits pass — cp.async double-buffered staging ===========
__global__ void __launch_bounds__(256) k1_logits(const float* __restrict__ logits,
                          const float* __restrict__ fg_mask,
                          const float* __restrict__ prot_mask,
                          const float* __restrict__ tw) {
    extern __shared__ float dbuf[];      // 2 x TILE_FLOATS = 56KB
    int b = blockIdx.y, blk = blockIdx.x;
    int tid = threadIdx.x, w = tid >> 5, t = tid & 31;

    __shared__ float tks[8][8];
    __shared__ float wsh_s[8];

    if (tid < K_) {
        float x = tw[tid];
        wsh_s[tid] = fmaxf(x, 0.0f) + log1pf(expf(-fabsf(x)));
    }

    int r0 = blk * 32;
    const float4* src0 = (const float4*)(logits + (size_t)(b * R_ + r0) * 896);
    unsigned int sbase = (unsigned int)__cvta_generic_to_shared(dbuf);

    // preload tile 0
    #pragma unroll
    for (int i = 0; i < 7; i++) {
        int idx = tid + 256 * i;
        cpasync16(sbase + idx * 16, src0 + idx);
    }
    cpasync_commit();

    __syncthreads();
    float wshr[K_];
    #pragma unroll
    for (int k = 0; k < K_; k++) wshr[k] = wsh_s[k];

    float fgc[4], mexfc[4];
    #pragma unroll
    for (int c = 0; c < 4; c++) {
        fgc[c] = fg_mask[b * F_ + t + 32 * c];
        mexfc[c] = __expf(-(1.0f - fgc[c]) * 1e9f);
    }

    float zc[4] = {0,0,0,0}, lc[4] = {0,0,0,0}, ab[4] = {0,0,0,0};
    float tk[K_];
    #pragma unroll
    for (int k = 0; k < K_; k++) tk[k] = 0.0f;

    for (int tile = 0; tile < 4; tile++) {
        // prefetch next tile into the other buffer
        if (tile < 3) {
            const float4* srcn = (const float4*)(logits + (size_t)(b * R_ + r0 + (tile + 1) * 8) * 896);
            unsigned int sb = sbase + ((tile + 1) & 1) * (TILE_FLOATS * 4);
            #pragma unroll
            for (int i = 0; i < 7; i++) {
                int idx = tid + 256 * i;
                cpasync16(sb + idx * 16, srcn + idx);
            }
            cpasync_commit();
            cpasync_wait<1>();
        } else {
            cpasync_wait<0>();
        }
        __syncthreads();

        const float* buf = dbuf + (tile & 1) * TILE_FLOATS;
        int r = r0 + tile * 8 + w;
        float pm = prot_mask[b * R_ + r];
        float mexr = __expf(-(1.0f - pm) * 1e9f);
        float rowS = 0.0f, rowE = 0.0f;
        float Ev[4];

        #pragma unroll
        for (int c = 0; c < 4; c++) {
            int fb = w * 896 + (t + 32 * c) * 7;     // lane stride 7: conflict-free
            float x0 = buf[fb+0], x1 = buf[fb+1], x2 = buf[fb+2], x3 = buf[fb+3];
            float x4 = buf[fb+4], x5 = buf[fb+5], x6 = buf[fb+6];
            float m = fmaxf(fmaxf(fmaxf(x0,x1),fmaxf(x2,x3)),fmaxf(fmaxf(x4,x5),x6));
            float e0=__expf(x0-m), e1=__expf(x1-m), e2=__expf(x2-m), e3=__expf(x3-m);
            float e4=__expf(x4-m), e5=__expf(x5-m), e6=__expf(x6-m);
            float s = e0+e1+e2+e3+e4+e5+e6;
            float inv = __fdividef(1.0f, s);
            float w0=e0*inv*wshr[0], w1=e1*inv*wshr[1], w2=e2*inv*wshr[2], w3=e3*inv*wshr[3];
            float w4=e4*inv*wshr[4], w5=e5*inv*wshr[5], w6=e6*inv*wshr[6];
            tk[0]+=w0; tk[1]+=w1; tk[2]+=w2; tk[3]+=w3; tk[4]+=w4; tk[5]+=w5; tk[6]+=w6;
            float Sv = w0+w1+w2+w3+w4+w5+w6;
            float Sm = Sv * pm * fgc[c];
            float E = __expf(Sm);
            E_g[(size_t)(b * R_ + r) * F_ + t + 32 * c] = E;
            Ev[c] = E;
            rowS += Sm; rowE += E * mexfc[c];
            zc[c] += E * mexr; lc[c] += Sm;
        }
        rowS = warpAllSum(rowS);
        rowE = warpAllSum(rowE);
        float ps = rowS * pm;
        if (t == 0) { pscore_g[b * R_ + r] = ps; Zrow_g[b * R_ + r] = rowE; }
        float coef = __fdividef(ps, rowE);
        #pragma unroll
        for (int c = 0; c < 4; c++) ab[c] += coef * Ev[c];

        __syncthreads();   // all reads of this buffer done before it is re-staged
    }

    #pragma unroll
    for (int k = 0; k < K_; k++) { float v = warpSum(tk[k]); if (t == 0) tks[w][k] = v; }
    #pragma unroll
    for (int c = 0; c < 4; c++) {
        dbuf[w * 128 + t + 32 * c]        = zc[c];
        dbuf[1024 + w * 128 + t + 32 * c] = lc[c];
        dbuf[2048 + w * 128 + t + 32 * c] = ab[c];
    }
    __syncthreads();
    if (tid < 128) {
        float s = 0.0f, s2 = 0.0f, s3 = 0.0f;
        #pragma unroll
        for (int ww = 0; ww < 8; ww++) {
            s  += dbuf[ww * 128 + tid];
            s2 += dbuf[1024 + ww * 128 + tid];
            s3 += dbuf[2048 + ww * 128 + tid];
        }
        Zcolp_g[(size_t)(b * NB1_ + blk) * F_ + tid]   = s;
        ligcolp_g[(size_t)(b * NB1_ + blk) * F_ + tid] = s2;
        abarp_g[(size_t)(b * NB1_ + blk) * F_ + tid]   = s3;
    } else if (tid < 128 + K_) {
        int k = tid - 128;
        float s = 0.0f;
        #pragma unroll
        for (int ww = 0; ww < 8; ww++) s += tks[ww][k];
        tstrp_g[(size_t)(b * NB1_ + blk) * 8 + k] = s;
    }
}

// ============ K3: lean E pass — craw + unscaled Pw/Cw partials =============
__global__ void __launch_bounds__(256, 6) k3_epass(const float* __restrict__ protein_emb,
                        const float* __restrict__ ligand_emb,
                        const float* __restrict__ fg_mask,
                        const float* __restrict__ prot_mask,
                        const float* __restrict__ Wr, const float* __restrict__ Wf,
                        const float* __restrict__ W1, const float* __restrict__ W2) {
    int b = blockIdx.y, blk = blockIdx.x;
    int tid = threadIdx.x, w = tid >> 5, t = tid & 31;
    int f = tid & 127, q = tid >> 7;

    __shared__ float lco_sm[128];
    __shared__ float zsm[2][128], lsm[2][128];
    __shared__ float stage[2048];

    // L2 prefetch of head weights + ligand (covers all lines across 512 blocks)
    {
        int gb = b * NB3_ + blk;                       // 0..511
        long gid = (long)gb * 256 + tid;               // 0..131071
        const long n1 = 4208;                          // W1 lines
        const long n2 = 4096;                          // W2 lines
        const long nr = 512;                           // Wr/Wf lines each
        const long nl = 8192;                          // ligand lines (1MB)
        if (gid < n1)                      l2pf((const char*)W1 + gid * 128);
        else if (gid < n1+n2)              l2pf((const char*)W2 + (gid-n1) * 128);
        else if (gid < n1+n2+nr)           l2pf((const char*)Wr + (gid-n1-n2) * 128);
        else if (gid < n1+n2+2*nr)         l2pf((const char*)Wf + (gid-n1-n2-nr) * 128);
        else if (gid < n1+n2+2*nr+nl)      l2pf((const char*)ligand_emb + (gid-n1-n2-2*nr) * 128);
    }

    // lcoef from k1 column partials
    float zs = 0.0f, ls = 0.0f;
    for (int s = q * 16; s < q * 16 + 16; s++) {
        zs += Zcolp_g[(size_t)(b * NB1_ + s) * F_ + f];
        ls += ligcolp_g[(size_t)(b * NB1_ + s) * F_ + f];
    }
    zsm[q][f] = zs; lsm[q][f] = ls;
    __syncthreads();
    if (tid < 128) {
        float Zc  = zsm[0][tid] + zsm[1][tid];
        float lgc = lsm[0][tid] + lsm[1][tid];
        lco_sm[tid] = __fdividef(lgc * fg_mask[b * F_ + tid], Zc);
    }
    __syncthreads();
    float lcoc[4];
    #pragma unroll
    for (int c = 0; c < 4; c++) lcoc[c] = lco_sm[t + 32 * c];

    // row loop: 8 warps x 4 rows
    float Pa[4] = {0,0,0,0}, Ca[4] = {0,0,0,0};
    int rbase = blk * 32 + w * 4;
    #pragma unroll
    for (int i = 0; i < 4; i++) {
        int r = rbase + i;
        float ps = pscore_g[b * R_ + r];
        float pm = prot_mask[b * R_ + r];
        float mexr = __expf(-(1.0f - pm) * 1e9f);
        float E[4], dv = 0.0f;
        #pragma unroll
        for (int c = 0; c < 4; c++) {
            E[c] = E_g[(size_t)(b * R_ + r) * F_ + t + 32 * c];
            dv += lcoc[c] * E[c];
        }
        float craw = mexr * warpAllSum(dv);
        #pragma unroll
        for (int c = 0; c < 4; c++) {
            float Pv = protein_emb[(size_t)(b * R_ + r) * D_ + t + 32 * c];
            Pa[c] += ps * Pv;
            Ca[c] += craw * Pv;
        }
    }

    __syncthreads();
    #pragma unroll
    for (int c = 0; c < 4; c++) {
        stage[w * 128 + t + 32 * c]        = Pa[c];
        stage[1024 + w * 128 + t + 32 * c] = Ca[c];
    }
    __syncthreads();
    if (tid < 128) {
        float s = 0.0f;
        #pragma unroll
        for (int ww = 0; ww < 8; ww++) s += stage[ww * 128 + tid];
        Pwp_g[(size_t)(b * NB3_ + blk) * D_ + tid] = s;
    } else {
        float s = 0.0f;
        #pragma unroll
        for (int ww = 0; ww < 8; ww++) s += stage[1024 + ww * 128 + f];
        Cwp_g[(size_t)(b * NB3_ + blk) * D_ + f] = s;
    }
}

// ============ KHEAD: pools + feat + norm + MLP (one block per batch) =======
__global__ void __launch_bounds__(512, 2) khead(const float* __restrict__ ligand_emb,
                        const float* __restrict__ fg_mask,
                        const float* __restrict__ Wr, const float* __restrict__ br,
                        const float* __restrict__ Wf, const float* __restrict__ bf,
                        const float* __restrict__ W1, const float* __restrict__ b1,
                        const float* __restrict__ W2, const float* __restrict__ b2,
                        const float* __restrict__ W3, const float* __restrict__ b3,
                        float* __restrict__ dout, int osz) {
    int b = blockIdx.x, tid = threadIdx.x, w = tid >> 5, t = tid & 31;
    int f = tid & 127, q = tid >> 7;

    __shared__ float red[32];
    __shared__ float big[2048];
    __shared__ float lw_sm[128], la_s[128];
    __shared__ float Pws[128], Cws[128];
    __shared__ float gs[128], Ls[128];
    __shared__ float feat[FEAT_ + 1];
    __shared__ float h1[H_], h2[H2_];
    __shared__ float tst[8];

    if (b == 0) for (int i = B_ + B_ * FEAT_ + tid; i < osz; i += 512) dout[i] = 0.0f;

    // psum
    float v = pscore_g[b * R_ + tid] + pscore_g[b * R_ + 512 + tid];
    float psum = blockReduceSum(v, red);
    float ip = __fdividef(1.0f, psum + 1e-8f);
    float spw = psum * ip;

    // ligcol sums -> lsum, lw
    {
        float ls = 0.0f;
        for (int s = q * 8; s < q * 8 + 8; s++) ls += ligcolp_g[(size_t)(b * NB1_ + s) * F_ + f];
        big[q * 128 + f] = ls;
    }
    __syncthreads();
    float lw0 = 0.0f;
    if (tid < 128) {
        float lgc = big[tid] + big[128+tid] + big[256+tid] + big[384+tid];
        lw0 = lgc * fg_mask[b * F_ + tid];
    }
    float lsum = blockReduceSum(lw0, red);
    float il = __fdividef(1.0f, lsum + 1e-8f);
    float slw = lsum * il;
    if (tid < 128) lw_sm[tid] = lw0 * il;

    // slot sums: abar (NB1 slots), Pw/Cw (NB3 slots)
    {
        float aA = 0.0f, aP = 0.0f, aC = 0.0f;
        #pragma unroll
        for (int s = 0; s < 8; s++) {
            int s1 = q * 8 + s;
            aA += abarp_g[(size_t)(b * NB1_ + s1) * F_ + f];
            aP += Pwp_g[(size_t)(b * NB3_ + s1) * D_ + f];
            aC += Cwp_g[(size_t)(b * NB3_ + s1) * D_ + f];
        }
        big[512 + q * 128 + f]  = aA;
        big[1024 + q * 128 + f] = aP;
        big[1536 + q * 128 + f] = aC;
    }
    __syncthreads();
    if (tid < 128) {
        float aA = big[512+tid] + big[640+tid] + big[768+tid] + big[896+tid];
        float aP = big[1024+tid] + big[1152+tid] + big[1280+tid] + big[1408+tid];
        float aC = big[1536+tid] + big[1664+tid] + big[1792+tid] + big[1920+tid];
        float fg = fg_mask[b * F_ + tid];
        float mexf = __expf(-(1.0f - fg) * 1e9f);
        la_s[tid] = aA * mexf * ip;
        Pws[tid] = aP * ip;
        Cws[tid] = aC * il;
    }
    if (tid < K_) {
        float s = 0.0f;
        #pragma unroll
        for (int s2 = 0; s2 < NB1_; s2++) s += tstrp_g[(size_t)(b * NB1_ + s2) * 8 + tid];
        tst[tid] = s;
    }
    __syncthreads();

    // ligand pooling: 4 f-chunks x 128 d
    float ag = 0.0f, aL = 0.0f;
    #pragma unroll 8
    for (int i = 0; i < 32; i++) {
        int ff = q * 32 + i;
        float lv = ligand_emb[(size_t)(b * F_ + ff) * D_ + f];
        ag += la_s[ff] * lv;
        aL += lw_sm[ff] * lv;
    }
    big[q * 128 + f] = ag;
    big[512 + q * 128 + f] = aL;
    __syncthreads();
    if (tid < 128) {
        gs[tid] = big[tid] + big[128+tid] + big[256+tid] + big[384+tid];
        Ls[tid] = big[512+tid] + big[640+tid] + big[768+tid] + big[896+tid];
    }
    __syncthreads();

    // feat rows: warps 0-7 -> Wr/gs, 8-15 -> Wf/Cws; 4 rows per iteration
    {
        const float* Wm = (w < 8) ? Wr : Wf;
        const float* vec = (w < 8) ? gs : Cws;
        int rb = (w & 7) * 16;
        #pragma unroll 1
        for (int i = 0; i < 4; i++) {
            int r0 = rb + i * 4;
            float p0=0.f,p1=0.f,p2=0.f,p3=0.f;
            #pragma unroll
            for (int u = 0; u < 4; u++) {
                int j = t + 32 * u;
                float g = vec[j];
                p0 += Wm[(r0+0)*D_ + j] * g;
                p1 += Wm[(r0+1)*D_ + j] * g;
                p2 += Wm[(r0+2)*D_ + j] * g;
                p3 += Wm[(r0+3)*D_ + j] * g;
            }
            p0 = warpSum(p0); p1 = warpSum(p1); p2 = warpSum(p2); p3 = warpSum(p3);
            if (t == 0) {
                if (w < 8) {
                    feat[r0+0] = Pws[r0+0] + p0 + spw * br[r0+0];
                    feat[r0+1] = Pws[r0+1] + p1 + spw * br[r0+1];
                    feat[r0+2] = Pws[r0+2] + p2 + spw * br[r0+2];
                    feat[r0+3] = Pws[r0+3] + p3 + spw * br[r0+3];
                } else {
                    feat[128+r0+0] = Ls[r0+0] + p0 + slw * bf[r0+0];
                    feat[128+r0+1] = Ls[r0+1] + p1 + slw * bf[r0+1];
                    feat[128+r0+2] = Ls[r0+2] + p2 + slw * bf[r0+2];
                    feat[128+r0+3] = Ls[r0+3] + p3 + slw * bf[r0+3];
                }
            }
        }
    }
    if (tid < K_) feat[2 * D_ + tid] = tst[tid];
    __syncthreads();

    // norm + normalized-feat output
    float sv = (tid < FEAT_) ? feat[tid] * feat[tid] : 0.0f;
    float nrm = blockReduceSum(sv, red);
    float inv = 1.0f / fmaxf(sqrtf(nrm), 1e-12f);
    if (tid < FEAT_) {
        int oi = B_ + b * FEAT_ + tid;
        if (oi < osz) dout[oi] = feat[tid] * inv;
    }

    // MLP layer 1: 512 rows, 32/warp, 4 per iteration
    {
        int rb = w * 32;
        #pragma unroll 1
        for (int i = 0; i < 8; i++) {
            int r0 = rb + i * 4;
            float p0=0.f,p1=0.f,p2=0.f,p3=0.f;
            #pragma unroll
            for (int u = 0; u < 8; u++) {
                int j = t + 32 * u;
                float fv = feat[j];
                p0 += W1[(r0+0)*FEAT_ + j] * fv;
                p1 += W1[(r0+1)*FEAT_ + j] * fv;
                p2 += W1[(r0+2)*FEAT_ + j] * fv;
                p3 += W1[(r0+3)*FEAT_ + j] * fv;
            }
            if (t < 7) {
                int j = 256 + t;
                float fv = feat[j];
                p0 += W1[(r0+0)*FEAT_ + j] * fv;
                p1 += W1[(r0+1)*FEAT_ + j] * fv;
                p2 += W1[(r0+2)*FEAT_ + j] * fv;
                p3 += W1[(r0+3)*FEAT_ + j] * fv;
            }
            p0 = warpSum(p0); p1 = warpSum(p1); p2 = warpSum(p2); p3 = warpSum(p3);
            if (t == 0) {
                h1[r0+0] = fmaxf(p0 + b1[r0+0], 0.0f);
                h1[r0+1] = fmaxf(p1 + b1[r0+1], 0.0f);
                h1[r0+2] = fmaxf(p2 + b1[r0+2], 0.0f);
                h1[r0+3] = fmaxf(p3 + b1[r0+3], 0.0f);
            }
        }
    }
    __syncthreads();

    // MLP layer 2: 256 rows, 16/warp, 2 per iteration
    {
        int rb = w * 16;
        #pragma unroll 1
        for (int i = 0; i < 8; i++) {
            int r0 = rb + i * 2;
            float p0=0.f,p1=0.f;
            #pragma unroll
            for (int u = 0; u < 16; u++) {
                int j = t + 32 * u;
                float hv = h1[j];
                p0 += W2[(r0+0)*H_ + j] * hv;
                p1 += W2[(r0+1)*H_ + j] * hv;
            }
            p0 = warpSum(p0); p1 = warpSum(p1);
            if (t == 0) {
                h2[r0+0] = fmaxf(p0 + b2[r0+0], 0.0f);
                h2[r0+1] = fmaxf(p1 + b2[r0+1], 0.0f);
            }
        }
    }
    __syncthreads();
    float pv = (tid < H2_) ? W3[tid] * h2[tid] : 0.0f;
    float pred = blockReduceSum(pv, red);
    if (tid == 0 && b < osz) dout[b] = pred + b3[0];
}

// ---------------- launch ----------------
extern "C" void kernel_launch(void* const* d_in, const int* in_sizes, int n_in,
                              void* d_out, int out_size) {
    const float* lig    = (const float*)d_in[0];
    const float* prot   = (const float*)d_in[1];
    const float* logits = (const float*)d_in[2];
    const float* fg     = (const float*)d_in[3];
    const float* pmsk   = (const float*)d_in[4];
    const float* tw     = (const float*)d_in[5];
    const float* Wr = (const float*)d_in[6];  const float* br = (const float*)d_in[7];
    const float* Wf = (const float*)d_in[8];  const float* bf = (const float*)d_in[9];
    const float* W1 = (const float*)d_in[10]; const float* b1 = (const float*)d_in[11];
    const float* W2 = (const float*)d_in[12]; const float* b2 = (const float*)d_in[13];
    const float* W3 = (const float*)d_in[14]; const float* b3 = (const float*)d_in[15];
    float* out = (float*)d_out;

    static int smem_set = 0;
    const int k1_smem = 2 * TILE_FLOATS * 4;   // 56KB
    if (!smem_set) {
        cudaFuncSetAttribute(k1_logits, cudaFuncAttributeMaxDynamicSharedMemorySize, k1_smem);
        smem_set = 1;
    }

    k1_logits<<<dim3(NB1_, B_), 256, k1_smem>>>(logits, fg, pmsk, tw);
    k3_epass<<<dim3(NB3_, B_), 256>>>(prot, lig, fg, pmsk, Wr, Wf, W1, W2);
    khead<<<B_, 512>>>(lig, fg, Wr, br, Wf, bf, W1, b1, W2, b2, W3, b3, out, out_size);
}